// round 2
// baseline (speedup 1.0000x reference)
#include <cuda_runtime.h>
#include <cuda_bf16.h>
#include <math.h>

// Problem constants (fixed by the dataset)
#define N_NODES 50000
#define N_EDGES 800000
#define D_IN 192          // IN_DIM = 2*64 + 64
#define D_OUT 64

// ---------------- scratch (no cudaMalloc allowed) ----------------
__device__ float g_h[(size_t)N_EDGES * D_OUT];   // 204.8 MB
__device__ float g_a[N_EDGES];
__device__ int   g_cnt[N_NODES];
__device__ int   g_offs[N_NODES];
__device__ int   g_cur[N_NODES];
__device__ int   g_csr[N_EDGES];
__device__ int   g_is64;   // 1 if indices buffer is int64, 0 if int32

// ---------------- helpers ----------------
__device__ __forceinline__ float mish(float x) {
    // stable softplus: max(x,0) + log1p(exp(-|x|))
    float sp = fmaxf(x, 0.0f) + log1pf(expf(-fabsf(x)));
    return x * tanhf(sp);
}

// ---------------- kernel 0: detect index dtype ----------------
// indices is [2, E]: row 0 = dst (values < 50000), row 1 = slot ids.
// If stored as int64 (little-endian, nonneg < 2^31), every odd 32-bit word
// is a zero high-word. If int32, odd words are random dst values.
__global__ void detect_kernel(const int* __restrict__ idx32) {
    if (threadIdx.x == 0 && blockIdx.x == 0) {
        bool is64 = true;
        for (int i = 1; i < 64; i += 2)
            if (idx32[i] != 0) { is64 = false; break; }
        g_is64 = is64 ? 1 : 0;
    }
}

// ---------------- kernel 1: fused GEMM (h = X W^T) + logits a = mish(h . w_att)
// Tile: 64 edges x 64 cols per iteration, micro-tile 4x4 per thread (16x16 threads).
// W (192x64) fully resident in smem; X tile 64x192 resident (K loop fully in smem).
#define XPAD 196  // 192 padded to break 32-bank alignment (192 % 32 == 0)

__global__ __launch_bounds__(256) void gemm_att_kernel(
    const float* __restrict__ X,      // [E,192]
    const float* __restrict__ W,      // [64,192] row-major (c,k)
    const float* __restrict__ w_att,  // [64]
    int n_edges)
{
    extern __shared__ float smem[];
    float* wsm = smem;                 // [192][64]  wsm[k*64 + c]
    float* xs  = smem + 192 * 64;      // [64][XPAD] xs[e*XPAD + k]

    const int tid = threadIdx.x;
    const int tx = tid & 15;           // col group: cols tx*4 .. tx*4+3
    const int ty = tid >> 4;           // edge group: edges ty*4 .. ty*4+3

    // Load W once per block: Wg[c*192+k] -> wsm[k*64+c]
    for (int l = tid; l < 192 * 64; l += 256) {
        int c = l / 192, k = l % 192;
        wsm[k * 64 + c] = W[l];
    }
    // per-thread attention weights for its 4 columns
    float wa0 = w_att[tx * 4 + 0];
    float wa1 = w_att[tx * 4 + 1];
    float wa2 = w_att[tx * 4 + 2];
    float wa3 = w_att[tx * 4 + 3];
    __syncthreads();

    const int n_tiles = n_edges / 64;  // 12500, exact
    for (int tile = blockIdx.x; tile < n_tiles; tile += gridDim.x) {
        __syncthreads();  // previous iteration's reads of xs are done
        // load 64x192 X tile: contiguous 12288 floats -> 3072 float4
        const float4* src = (const float4*)(X + (size_t)tile * 64 * 192);
        for (int l = tid; l < 64 * (192 / 4); l += 256) {
            int e = l / 48;            // 48 float4 per row
            int k4 = l % 48;
            float4 v = src[l];
            float* dstp = &xs[e * XPAD + k4 * 4];
            dstp[0] = v.x; dstp[1] = v.y; dstp[2] = v.z; dstp[3] = v.w;
        }
        __syncthreads();

        float acc[4][4];
#pragma unroll
        for (int i = 0; i < 4; i++)
#pragma unroll
            for (int j = 0; j < 4; j++) acc[i][j] = 0.0f;

#pragma unroll 4
        for (int k4 = 0; k4 < 48; k4++) {
            float4 xv[4];
#pragma unroll
            for (int i = 0; i < 4; i++)
                xv[i] = *(const float4*)&xs[(ty * 4 + i) * XPAD + k4 * 4];
            float4 wv[4];
#pragma unroll
            for (int kk = 0; kk < 4; kk++)
                wv[kk] = *(const float4*)&wsm[(k4 * 4 + kk) * 64 + tx * 4];
#pragma unroll
            for (int kk = 0; kk < 4; kk++) {
                float xk[4] = { (&xv[0].x)[kk], (&xv[1].x)[kk],
                                (&xv[2].x)[kk], (&xv[3].x)[kk] };
#pragma unroll
                for (int i = 0; i < 4; i++) {
                    acc[i][0] = fmaf(xk[i], wv[kk].x, acc[i][0]);
                    acc[i][1] = fmaf(xk[i], wv[kk].y, acc[i][1]);
                    acc[i][2] = fmaf(xk[i], wv[kk].z, acc[i][2]);
                    acc[i][3] = fmaf(xk[i], wv[kk].w, acc[i][3]);
                }
            }
        }

        // write h and compute attention logits
        const int e0 = tile * 64 + ty * 4;
#pragma unroll
        for (int i = 0; i < 4; i++) {
            float4 v = make_float4(acc[i][0], acc[i][1], acc[i][2], acc[i][3]);
            *(float4*)&g_h[(size_t)(e0 + i) * 64 + tx * 4] = v;

            float p = acc[i][0] * wa0 + acc[i][1] * wa1 +
                      acc[i][2] * wa2 + acc[i][3] * wa3;
            // butterfly-sum over the 16 tx lanes (lane bits 0..3)
#pragma unroll
            for (int m = 8; m >= 1; m >>= 1)
                p += __shfl_xor_sync(0xffffffffu, p, m);
            if (tx == 0) g_a[e0 + i] = mish(p);
        }
    }
}

// ---------------- kernel 2a: zero counts
__global__ void zero_cnt_kernel() {
    int i = blockIdx.x * blockDim.x + threadIdx.x;
    if (i < N_NODES) g_cnt[i] = 0;
}

// ---------------- kernel 2b: histogram of destination nodes
__global__ void hist_kernel(const int* __restrict__ idx32, int n_edges) {
    int e = blockIdx.x * blockDim.x + threadIdx.x;
    if (e < n_edges) {
        int d = idx32[g_is64 ? (2 * e) : e];
        atomicAdd(&g_cnt[d], 1);
    }
}

// ---------------- kernel 2c: exclusive scan (single block, 1024 threads)
__global__ __launch_bounds__(1024) void scan_kernel(int n) {
    __shared__ int sm[1024];
    const int t = threadIdx.x;
    const int CH = (n + 1023) / 1024;
    const int lo = t * CH;
    const int hi = min(lo + CH, n);
    int s = 0;
    for (int i = lo; i < hi; i++) s += g_cnt[i];
    sm[t] = s;
    __syncthreads();
    for (int d = 1; d < 1024; d <<= 1) {
        int v = (t >= d) ? sm[t - d] : 0;
        __syncthreads();
        sm[t] += v;
        __syncthreads();
    }
    int pre = (t == 0) ? 0 : sm[t - 1];
    for (int i = lo; i < hi; i++) {
        g_offs[i] = pre;
        g_cur[i] = pre;
        pre += g_cnt[i];
    }
}

// ---------------- kernel 2d: fill CSR edge lists
__global__ void fill_kernel(const int* __restrict__ idx32, int n_edges) {
    int e = blockIdx.x * blockDim.x + threadIdx.x;
    if (e < n_edges) {
        int d = idx32[g_is64 ? (2 * e) : e];
        int pos = atomicAdd(&g_cur[d], 1);
        g_csr[pos] = e;
    }
}

// ---------------- kernel 3: warp-per-node segment softmax + weighted aggregation
__global__ __launch_bounds__(256) void aggregate_kernel(
    float* __restrict__ out, int n_nodes)
{
    const int node = (blockIdx.x * blockDim.x + threadIdx.x) >> 5;
    if (node >= n_nodes) return;
    const int lane = threadIdx.x & 31;
    const int start = g_offs[node];
    const int deg = g_cnt[node];

    // pass A: max logit
    float mx = -INFINITY;
    for (int i = lane; i < deg; i += 32)
        mx = fmaxf(mx, g_a[g_csr[start + i]]);
#pragma unroll
    for (int m = 16; m >= 1; m >>= 1)
        mx = fmaxf(mx, __shfl_xor_sync(0xffffffffu, mx, m));

    // pass B: denom
    float s = 0.0f;
    for (int i = lane; i < deg; i += 32)
        s += expf(g_a[g_csr[start + i]] - mx);
#pragma unroll
    for (int m = 16; m >= 1; m >>= 1)
        s += __shfl_xor_sync(0xffffffffu, s, m);
    const float inv = (deg > 0) ? (1.0f / s) : 0.0f;

    // pass C: weighted accumulate (each lane owns 2 of 64 columns)
    float2 acc = make_float2(0.0f, 0.0f);
    for (int i = 0; i < deg; i++) {
        int e = g_csr[start + i];
        float p = expf(g_a[e] - mx) * inv;
        float2 hv = *(const float2*)&g_h[(size_t)e * 64 + lane * 2];
        acc.x = fmaf(hv.x, p, acc.x);
        acc.y = fmaf(hv.y, p, acc.y);
    }
    *(float2*)&out[(size_t)node * 64 + lane * 2] = acc;
}

// ---------------- launch ----------------
extern "C" void kernel_launch(void* const* d_in, const int* in_sizes, int n_in,
                              void* d_out, int out_size) {
    const float* X = (const float*)d_in[0];
    const int* idx32 = (const int*)d_in[1];   // [2,E]; dtype detected on device
    const float* W = (const float*)d_in[2];
    const float* watt = (const float*)d_in[3];
    float* out = (float*)d_out;

    const int n_edges = in_sizes[0] / D_IN;       // 800000
    const int n_nodes = out_size / D_OUT;         // 50000

    const int smem_bytes = (192 * 64 + 64 * XPAD) * (int)sizeof(float); // 99328
    cudaFuncSetAttribute(gemm_att_kernel,
                         cudaFuncAttributeMaxDynamicSharedMemorySize,
                         smem_bytes);

    detect_kernel<<<1, 32>>>(idx32);
    gemm_att_kernel<<<304, 256, smem_bytes>>>(X, W, watt, n_edges);
    zero_cnt_kernel<<<(N_NODES + 255) / 256, 256>>>();
    hist_kernel<<<(n_edges + 255) / 256, 256>>>(idx32, n_edges);
    scan_kernel<<<1, 1024>>>(n_nodes);
    fill_kernel<<<(n_edges + 255) / 256, 256>>>(idx32, n_edges);
    aggregate_kernel<<<(n_nodes * 32 + 255) / 256, 256>>>(out, n_nodes);
}

// round 3
// speedup vs baseline: 1.3802x; 1.3802x over previous
#include <cuda_runtime.h>
#include <cuda_bf16.h>
#include <math.h>

#define N_NODES 50000
#define N_EDGES 800000
#define D_IN 192
#define D_OUT 64

// ---------------- scratch (no cudaMalloc allowed) ----------------
__device__ float g_a[N_EDGES];
__device__ float g_u[D_IN];
__device__ float g_xagg[(size_t)N_NODES * D_IN];   // 38.4 MB
__device__ int   g_cnt[N_NODES];
__device__ int   g_offs[N_NODES];
__device__ int   g_cur[N_NODES];
__device__ int   g_csr[N_EDGES];
__device__ int   g_is64;

__device__ __forceinline__ float mish(float x) {
    float sp = fmaxf(x, 0.0f) + log1pf(expf(-fabsf(x)));
    return x * tanhf(sp);
}

// ---------------- kernel 0: detect index dtype (int64 vs int32) ------------
__global__ void detect_kernel(const int* __restrict__ idx32) {
    if (threadIdx.x == 0 && blockIdx.x == 0) {
        bool is64 = true;
        for (int i = 1; i < 64; i += 2)
            if (idx32[i] != 0) { is64 = false; break; }
        g_is64 = is64 ? 1 : 0;
    }
}

// ---------------- kernel 1: u = W^T w_att  (192 threads) -------------------
__global__ void u_kernel(const float* __restrict__ W,
                         const float* __restrict__ watt) {
    int k = threadIdx.x;
    if (k < D_IN) {
        float s = 0.0f;
        for (int c = 0; c < D_OUT; c++)
            s = fmaf(W[c * D_IN + k], watt[c], s);
        g_u[k] = s;
    }
}

// ---------------- kernel 2: logits a[e] = mish(X[e] . u)  ------------------
// Block = 256 threads handles 64 edges. X tile staged in smem (coalesced
// float4 loads), 4 threads per edge each summing 48 contiguous k's.
#define XPAD 196
__global__ __launch_bounds__(256) void logits_kernel(
    const float* __restrict__ X, int n_edges)
{
    extern __shared__ float smem[];
    float* xs = smem;               // [64][XPAD]
    float* us = smem + 64 * XPAD;   // [192]

    const int tid = threadIdx.x;
    if (tid < D_IN) us[tid] = g_u[tid];

    const int tile = blockIdx.x;
    const float4* src = (const float4*)(X + (size_t)tile * 64 * D_IN);
    for (int l = tid; l < 64 * 48; l += 256) {
        int e = l / 48, k4 = l % 48;
        *(float4*)&xs[e * XPAD + k4 * 4] = src[l];
    }
    __syncthreads();

    const int e = tid >> 2;       // 0..63
    const int q = tid & 3;        // quarter of the row
    const float* xp = &xs[e * XPAD + q * 48];
    const float* up = &us[q * 48];
    float s = 0.0f;
#pragma unroll
    for (int i = 0; i < 48; i++) s = fmaf(xp[i], up[i], s);
    s += __shfl_xor_sync(0xffffffffu, s, 1);
    s += __shfl_xor_sync(0xffffffffu, s, 2);
    if (q == 0) {
        int ge = tile * 64 + e;
        if (ge < n_edges) g_a[ge] = mish(s);
    }
}

// ---------------- kernel 3a: zero counts -----------------------------------
__global__ void zero_cnt_kernel() {
    int i = blockIdx.x * blockDim.x + threadIdx.x;
    if (i < N_NODES) g_cnt[i] = 0;
}

// ---------------- kernel 3b: histogram of dst ------------------------------
__global__ void hist_kernel(const int* __restrict__ idx32, int n_edges) {
    int e = blockIdx.x * blockDim.x + threadIdx.x;
    if (e < n_edges) {
        int d = idx32[g_is64 ? (2 * e) : e];
        atomicAdd(&g_cnt[d], 1);
    }
}

// ---------------- kernel 3c: exclusive scan --------------------------------
__global__ __launch_bounds__(1024) void scan_kernel(int n) {
    __shared__ int sm[1024];
    const int t = threadIdx.x;
    const int CH = (n + 1023) / 1024;
    const int lo = t * CH;
    const int hi = min(lo + CH, n);
    int s = 0;
    for (int i = lo; i < hi; i++) s += g_cnt[i];
    sm[t] = s;
    __syncthreads();
    for (int d = 1; d < 1024; d <<= 1) {
        int v = (t >= d) ? sm[t - d] : 0;
        __syncthreads();
        sm[t] += v;
        __syncthreads();
    }
    int pre = (t == 0) ? 0 : sm[t - 1];
    for (int i = lo; i < hi; i++) {
        g_offs[i] = pre;
        g_cur[i] = pre;
        pre += g_cnt[i];
    }
}

// ---------------- kernel 3d: fill CSR ---------------------------------------
__global__ void fill_kernel(const int* __restrict__ idx32, int n_edges) {
    int e = blockIdx.x * blockDim.x + threadIdx.x;
    if (e < n_edges) {
        int d = idx32[g_is64 ? (2 * e) : e];
        int pos = atomicAdd(&g_cur[d], 1);
        g_csr[pos] = e;
    }
}

// ---------------- kernel 4: warp-per-node softmax + weighted X aggregation -
// xagg[n] = sum_e p_e * X[e,:]   (192-wide). Each lane owns 6 of 192 cols.
__global__ __launch_bounds__(256) void aggregate_kernel(
    const float* __restrict__ X, int n_nodes)
{
    const int node = (blockIdx.x * blockDim.x + threadIdx.x) >> 5;
    if (node >= n_nodes) return;
    const int lane = threadIdx.x & 31;
    const int start = g_offs[node];
    const int deg = g_cnt[node];

    // pass A: max logit
    float mx = -INFINITY;
    for (int i = lane; i < deg; i += 32)
        mx = fmaxf(mx, g_a[g_csr[start + i]]);
#pragma unroll
    for (int m = 16; m >= 1; m >>= 1)
        mx = fmaxf(mx, __shfl_xor_sync(0xffffffffu, mx, m));

    // pass B: denom
    float s = 0.0f;
    for (int i = lane; i < deg; i += 32)
        s += expf(g_a[g_csr[start + i]] - mx);
#pragma unroll
    for (int m = 16; m >= 1; m >>= 1)
        s += __shfl_xor_sync(0xffffffffu, s, m);
    const float inv = (deg > 0) ? (1.0f / s) : 0.0f;

    // pass C: weighted accumulate of X rows.
    // Lane l computes p for edge (base+l) once; broadcast via shfl.
    float2 a0 = make_float2(0.f, 0.f);
    float2 a1 = make_float2(0.f, 0.f);
    float2 a2 = make_float2(0.f, 0.f);
    for (int base = 0; base < deg; base += 32) {
        int i = base + lane;
        int el = 0;
        float pl = 0.0f;
        if (i < deg) {
            el = g_csr[start + i];
            pl = expf(g_a[el] - mx) * inv;
        }
        int cnt = min(32, deg - base);
        for (int j = 0; j < cnt; j++) {
            int e = __shfl_sync(0xffffffffu, el, j);
            float p = __shfl_sync(0xffffffffu, pl, j);
            const float2* xr = (const float2*)(X + (size_t)e * D_IN + lane * 6);
            float2 v0 = xr[0], v1 = xr[1], v2 = xr[2];
            a0.x = fmaf(v0.x, p, a0.x); a0.y = fmaf(v0.y, p, a0.y);
            a1.x = fmaf(v1.x, p, a1.x); a1.y = fmaf(v1.y, p, a1.y);
            a2.x = fmaf(v2.x, p, a2.x); a2.y = fmaf(v2.y, p, a2.y);
        }
    }
    float* dst = &g_xagg[(size_t)node * D_IN + lane * 6];
    ((float2*)dst)[0] = a0;
    ((float2*)dst)[1] = a1;
    ((float2*)dst)[2] = a2;
}

// ---------------- kernel 5: out = xagg @ W^T  [50000,192]x[192,64] ---------
// Block: 256 threads, 32-node tile. Thread = 2 cols x 4 nodes.
__global__ __launch_bounds__(256) void out_gemm_kernel(
    const float* __restrict__ W, float* __restrict__ out, int n_nodes)
{
    extern __shared__ float smem[];
    float* wsm = smem;              // [192][64] wsm[k*64+c]
    float* xs = smem + 192 * 64;    // [32][192]

    const int tid = threadIdx.x;
    for (int l = tid; l < 192 * 64; l += 256) {
        int c = l / 192, k = l % 192;
        wsm[k * 64 + c] = W[l];
    }
    const int n0 = blockIdx.x * 32;
    for (int l = tid; l < 32 * 192; l += 256) {
        int r = l / 192, k = l % 192;
        xs[r * 192 + k] = (n0 + r < n_nodes)
                        ? g_xagg[(size_t)(n0 + r) * 192 + k] : 0.0f;
    }
    __syncthreads();

    const int c2 = tid & 31;        // cols c2*2, c2*2+1
    const int rg = tid >> 5;        // node group 0..7 -> nodes rg, rg+8, rg+16, rg+24
    float o[4][2];
#pragma unroll
    for (int j = 0; j < 4; j++) { o[j][0] = 0.f; o[j][1] = 0.f; }

    for (int k4 = 0; k4 < 48; k4++) {
        float4 xv[4];
#pragma unroll
        for (int j = 0; j < 4; j++)
            xv[j] = *(const float4*)&xs[(rg + j * 8) * 192 + k4 * 4];
#pragma unroll
        for (int kk = 0; kk < 4; kk++) {
            float2 wv = *(const float2*)&wsm[(k4 * 4 + kk) * 64 + c2 * 2];
#pragma unroll
            for (int j = 0; j < 4; j++) {
                float xk = (&xv[j].x)[kk];
                o[j][0] = fmaf(xk, wv.x, o[j][0]);
                o[j][1] = fmaf(xk, wv.y, o[j][1]);
            }
        }
    }
#pragma unroll
    for (int j = 0; j < 4; j++) {
        int n = n0 + rg + j * 8;
        if (n < n_nodes)
            *(float2*)&out[(size_t)n * 64 + c2 * 2] = make_float2(o[j][0], o[j][1]);
    }
}

// ---------------- launch -----------------------------------------------------
extern "C" void kernel_launch(void* const* d_in, const int* in_sizes, int n_in,
                              void* d_out, int out_size) {
    const float* X = (const float*)d_in[0];
    const int* idx32 = (const int*)d_in[1];
    const float* W = (const float*)d_in[2];
    const float* watt = (const float*)d_in[3];
    float* out = (float*)d_out;

    const int n_edges = in_sizes[0] / D_IN;   // 800000
    const int n_nodes = out_size / D_OUT;     // 50000

    const int logits_smem = (64 * XPAD + 192) * (int)sizeof(float);      // 50944
    const int outg_smem = (192 * 64 + 32 * 192) * (int)sizeof(float);    // 73728
    cudaFuncSetAttribute(logits_kernel,
                         cudaFuncAttributeMaxDynamicSharedMemorySize, logits_smem);
    cudaFuncSetAttribute(out_gemm_kernel,
                         cudaFuncAttributeMaxDynamicSharedMemorySize, outg_smem);

    detect_kernel<<<1, 32>>>(idx32);
    u_kernel<<<1, 192>>>(W, watt);
    logits_kernel<<<(n_edges + 63) / 64, 256, logits_smem>>>(X, n_edges);
    zero_cnt_kernel<<<(N_NODES + 255) / 256, 256>>>();
    hist_kernel<<<(n_edges + 255) / 256, 256>>>(idx32, n_edges);
    scan_kernel<<<1, 1024>>>(n_nodes);
    fill_kernel<<<(n_edges + 255) / 256, 256>>>(idx32, n_edges);
    aggregate_kernel<<<(n_nodes * 32 + 255) / 256, 256>>>(X, n_nodes);
    out_gemm_kernel<<<(n_nodes + 31) / 32, 256, outg_smem>>>(W, out, n_nodes);
}

// round 4
// speedup vs baseline: 1.6807x; 1.2178x over previous
#include <cuda_runtime.h>
#include <cuda_bf16.h>
#include <math.h>

#define N_NODES 50000
#define N_EDGES 800000
#define D_IN 192
#define D_OUT 64

// ---------------- scratch ----------------
__device__ float    g_a[N_EDGES];       // logits
__device__ float    g_ea[N_EDGES];      // exp(a - gmax)
__device__ float    g_u[D_IN];          // W^T w_att
__device__ float    g_denom[N_NODES];
__device__ float    g_xagg[(size_t)N_NODES * D_IN];   // 38.4 MB
__device__ int      g_cnt[N_NODES];
__device__ int      g_offs[N_NODES];
__device__ int      g_cur[N_NODES];
__device__ int      g_csr[N_EDGES];
__device__ int      g_is64;
__device__ unsigned g_gmax;             // ordered-float max

__device__ __forceinline__ float mish(float x) {
    float sp = fmaxf(x, 0.0f) + log1pf(expf(-fabsf(x)));
    return x * tanhf(sp);
}
__device__ __forceinline__ unsigned f2o(float f) {
    unsigned b = __float_as_uint(f);
    return b ^ ((unsigned)((int)b >> 31) | 0x80000000u);
}
__device__ __forceinline__ float o2f(unsigned k) {
    unsigned b = (k & 0x80000000u) ? (k ^ 0x80000000u) : ~k;
    return __uint_as_float(b);
}

// ---------------- kernel 1: init (zero counters, u = W^T w_att, dtype detect)
__global__ void init_kernel(const float* __restrict__ W,
                            const float* __restrict__ watt,
                            const int* __restrict__ idx32) {
    int i = blockIdx.x * blockDim.x + threadIdx.x;
    if (i < N_NODES) { g_cnt[i] = 0; g_denom[i] = 0.0f; }
    if (blockIdx.x == 0) {
        int t = threadIdx.x;
        if (t < D_IN) {
            float s = 0.0f;
            for (int c = 0; c < D_OUT; c++)
                s = fmaf(W[c * D_IN + t], watt[c], s);
            g_u[t] = s;
        } else if (t == 192) {
            bool is64 = true;
            for (int j = 1; j < 64; j += 2)
                if (idx32[j] != 0) { is64 = false; break; }
            g_is64 = is64 ? 1 : 0;
        } else if (t == 193) {
            g_gmax = 0u;   // ordered-float -infinity sentinel
        }
    }
}

// ---------------- kernel 2: histogram of dst ------------------------------
__global__ void hist_kernel(const int* __restrict__ idx32, int n_edges) {
    int e = blockIdx.x * blockDim.x + threadIdx.x;
    if (e < n_edges) {
        int d = idx32[g_is64 ? (2 * e) : e];
        atomicAdd(&g_cnt[d], 1);
    }
}

// ---------------- kernel 3: exclusive scan --------------------------------
__global__ __launch_bounds__(1024) void scan_kernel(int n) {
    __shared__ int sm[1024];
    const int t = threadIdx.x;
    const int CH = (n + 1023) / 1024;
    const int lo = t * CH;
    const int hi = min(lo + CH, n);
    int s = 0;
    for (int i = lo; i < hi; i++) s += g_cnt[i];
    sm[t] = s;
    __syncthreads();
    for (int d = 1; d < 1024; d <<= 1) {
        int v = (t >= d) ? sm[t - d] : 0;
        __syncthreads();
        sm[t] += v;
        __syncthreads();
    }
    int pre = (t == 0) ? 0 : sm[t - 1];
    for (int i = lo; i < hi; i++) {
        g_offs[i] = pre;
        g_cur[i] = pre;
        pre += g_cnt[i];
    }
}

// ---------------- kernel 4 (PROFILED SLOT): logits a[e]=mish(X[e].u), gmax -
// Warp per 2 edges; lane loads 3 float2 per edge (coalesced LDG.64),
// u in registers, butterfly reduce; two edges interleaved for ILP.
__global__ __launch_bounds__(256) void logits_kernel(
    const float* __restrict__ X, int n_edges)
{
    const int lane = threadIdx.x & 31;
    const int wid = (blockIdx.x * blockDim.x + threadIdx.x) >> 5;
    const int n_warps = (gridDim.x * blockDim.x) >> 5;

    // u as 3 float2 per lane: covers 96 float2 = 192 floats
    const float2* u2 = (const float2*)g_u;
    float2 ua = u2[lane];
    float2 ub = u2[32 + lane];
    float2 uc = u2[64 + lane];

    float wmax = -INFINITY;
    const float2* X2 = (const float2*)X;

    for (int e = wid * 2; e < n_edges; e += n_warps * 2) {
        const float2* r0 = X2 + (size_t)e * 96;
        const float2* r1 = r0 + 96;
        float2 a0 = r0[lane],      b0 = r0[32 + lane], c0 = r0[64 + lane];
        float2 a1 = r1[lane],      b1 = r1[32 + lane], c1 = r1[64 + lane];

        float s0 = a0.x * ua.x + a0.y * ua.y;
        float s1 = a1.x * ua.x + a1.y * ua.y;
        s0 = fmaf(b0.x, ub.x, fmaf(b0.y, ub.y, s0));
        s1 = fmaf(b1.x, ub.x, fmaf(b1.y, ub.y, s1));
        s0 = fmaf(c0.x, uc.x, fmaf(c0.y, uc.y, s0));
        s1 = fmaf(c1.x, uc.x, fmaf(c1.y, uc.y, s1));
#pragma unroll
        for (int m = 16; m >= 1; m >>= 1) {
            s0 += __shfl_xor_sync(0xffffffffu, s0, m);
            s1 += __shfl_xor_sync(0xffffffffu, s1, m);
        }
        float m0 = mish(s0), m1 = mish(s1);
        if (lane == 0) { g_a[e] = m0; g_a[e + 1] = m1; }
        wmax = fmaxf(wmax, fmaxf(m0, m1));
    }
    if (lane == 0) atomicMax(&g_gmax, f2o(wmax));
}

// ---------------- kernel 5: fill CSR + e_e + per-node denom ----------------
__global__ void fill_kernel(const int* __restrict__ idx32, int n_edges) {
    int e = blockIdx.x * blockDim.x + threadIdx.x;
    if (e < n_edges) {
        float gmax = o2f(g_gmax);
        float ee = expf(g_a[e] - gmax);
        g_ea[e] = ee;
        int d = idx32[g_is64 ? (2 * e) : e];
        atomicAdd(&g_denom[d], ee);
        int pos = atomicAdd(&g_cur[d], 1);
        g_csr[pos] = e;
    }
}

// ---------------- kernel 6: warp-per-node weighted X aggregation -----------
__global__ __launch_bounds__(256) void aggregate_kernel(
    const float* __restrict__ X, int n_nodes)
{
    const int node = (blockIdx.x * blockDim.x + threadIdx.x) >> 5;
    if (node >= n_nodes) return;
    const int lane = threadIdx.x & 31;
    const int start = g_offs[node];
    const int deg = g_cnt[node];
    const float inv = (deg > 0) ? (1.0f / g_denom[node]) : 0.0f;

    float2 a0 = make_float2(0.f, 0.f);
    float2 a1 = make_float2(0.f, 0.f);
    float2 a2 = make_float2(0.f, 0.f);
    const float2* X2 = (const float2*)X;

    for (int base = 0; base < deg; base += 32) {
        int i = base + lane;
        int el = 0;
        float wl = 0.0f;
        if (i < deg) {
            el = g_csr[start + i];
            wl = g_ea[el] * inv;
        }
        int cnt = min(32, deg - base);
        int j = 0;
        // 2-way unrolled gather for MLP
        for (; j + 2 <= cnt; j += 2) {
            int eA = __shfl_sync(0xffffffffu, el, j);
            float pA = __shfl_sync(0xffffffffu, wl, j);
            int eB = __shfl_sync(0xffffffffu, el, j + 1);
            float pB = __shfl_sync(0xffffffffu, wl, j + 1);
            const float2* rA = X2 + (size_t)eA * 96 + lane * 3;
            const float2* rB = X2 + (size_t)eB * 96 + lane * 3;
            float2 vA0 = rA[0], vA1 = rA[1], vA2 = rA[2];
            float2 vB0 = rB[0], vB1 = rB[1], vB2 = rB[2];
            a0.x = fmaf(vA0.x, pA, a0.x); a0.y = fmaf(vA0.y, pA, a0.y);
            a1.x = fmaf(vA1.x, pA, a1.x); a1.y = fmaf(vA1.y, pA, a1.y);
            a2.x = fmaf(vA2.x, pA, a2.x); a2.y = fmaf(vA2.y, pA, a2.y);
            a0.x = fmaf(vB0.x, pB, a0.x); a0.y = fmaf(vB0.y, pB, a0.y);
            a1.x = fmaf(vB1.x, pB, a1.x); a1.y = fmaf(vB1.y, pB, a1.y);
            a2.x = fmaf(vB2.x, pB, a2.x); a2.y = fmaf(vB2.y, pB, a2.y);
        }
        for (; j < cnt; j++) {
            int e = __shfl_sync(0xffffffffu, el, j);
            float p = __shfl_sync(0xffffffffu, wl, j);
            const float2* xr = X2 + (size_t)e * 96 + lane * 3;
            float2 v0 = xr[0], v1 = xr[1], v2 = xr[2];
            a0.x = fmaf(v0.x, p, a0.x); a0.y = fmaf(v0.y, p, a0.y);
            a1.x = fmaf(v1.x, p, a1.x); a1.y = fmaf(v1.y, p, a1.y);
            a2.x = fmaf(v2.x, p, a2.x); a2.y = fmaf(v2.y, p, a2.y);
        }
    }
    float2* dst = (float2*)&g_xagg[(size_t)node * D_IN + lane * 6];
    dst[0] = a0; dst[1] = a1; dst[2] = a2;
}

// ---------------- kernel 7: out = xagg @ W^T ------------------------------
__global__ __launch_bounds__(256) void out_gemm_kernel(
    const float* __restrict__ W, float* __restrict__ out, int n_nodes)
{
    extern __shared__ float smem[];
    float* wsm = smem;              // [192][64] wsm[k*64+c]
    float* xs = smem + 192 * 64;    // [32][192]

    const int tid = threadIdx.x;
    for (int l = tid; l < 192 * 64; l += 256) {
        int c = l / 192, k = l % 192;
        wsm[k * 64 + c] = W[l];
    }
    const int n0 = blockIdx.x * 32;
    for (int l = tid; l < 32 * 192; l += 256) {
        int r = l / 192, k = l % 192;
        xs[r * 192 + k] = (n0 + r < n_nodes)
                        ? g_xagg[(size_t)(n0 + r) * 192 + k] : 0.0f;
    }
    __syncthreads();

    const int c2 = tid & 31;
    const int rg = tid >> 5;
    float o[4][2];
#pragma unroll
    for (int j = 0; j < 4; j++) { o[j][0] = 0.f; o[j][1] = 0.f; }

    for (int k4 = 0; k4 < 48; k4++) {
        float4 xv[4];
#pragma unroll
        for (int j = 0; j < 4; j++)
            xv[j] = *(const float4*)&xs[(rg + j * 8) * 192 + k4 * 4];
#pragma unroll
        for (int kk = 0; kk < 4; kk++) {
            float2 wv = *(const float2*)&wsm[(k4 * 4 + kk) * 64 + c2 * 2];
#pragma unroll
            for (int j = 0; j < 4; j++) {
                float xk = (&xv[j].x)[kk];
                o[j][0] = fmaf(xk, wv.x, o[j][0]);
                o[j][1] = fmaf(xk, wv.y, o[j][1]);
            }
        }
    }
#pragma unroll
    for (int j = 0; j < 4; j++) {
        int n = n0 + rg + j * 8;
        if (n < n_nodes)
            *(float2*)&out[(size_t)n * 64 + c2 * 2] = make_float2(o[j][0], o[j][1]);
    }
}

// ---------------- launch ----------------------------------------------------
extern "C" void kernel_launch(void* const* d_in, const int* in_sizes, int n_in,
                              void* d_out, int out_size) {
    const float* X = (const float*)d_in[0];
    const int* idx32 = (const int*)d_in[1];
    const float* W = (const float*)d_in[2];
    const float* watt = (const float*)d_in[3];
    float* out = (float*)d_out;

    const int n_edges = in_sizes[0] / D_IN;   // 800000
    const int n_nodes = out_size / D_OUT;     // 50000

    const int outg_smem = (192 * 64 + 32 * 192) * (int)sizeof(float);  // 73728
    cudaFuncSetAttribute(out_gemm_kernel,
                         cudaFuncAttributeMaxDynamicSharedMemorySize, outg_smem);

    init_kernel<<<(N_NODES + 255) / 256, 256>>>(W, watt, idx32);       // 1
    hist_kernel<<<(n_edges + 255) / 256, 256>>>(idx32, n_edges);       // 2
    scan_kernel<<<1, 1024>>>(n_nodes);                                 // 3
    logits_kernel<<<1184, 256>>>(X, n_edges);                          // 4 (profiled)
    fill_kernel<<<(n_edges + 255) / 256, 256>>>(idx32, n_edges);       // 5
    aggregate_kernel<<<(n_nodes * 32 + 255) / 256, 256>>>(X, n_nodes); // 6
    out_gemm_kernel<<<(n_nodes + 31) / 32, 256, outg_smem>>>(W, out, n_nodes); // 7
}